// round 13
// baseline (speedup 1.0000x reference)
#include <cuda_runtime.h>

#define NN 32768   // columns
#define MM 512     // rows of A / X
#define KK 32      // inner dim / output rows
#define NITER 200  // must match reference trajectory exactly
#define POWER_ITERS 40
#define YS 36      // sY row stride in floats

typedef unsigned long long u64;

// ---- device-global scratch (no allocations allowed) ----
__device__ float g_step;
__device__ float g_mu[NITER];                   // precomputed Nesterov momentum factors
__device__ __align__(16) float g_AtA[KK][KK];   // symmetric Gram matrix
__device__ float g_nAtX[KK][NN];                // negated A^T X, row-major

// ---- packed f32x2 helpers (sm_100a) ----
__device__ __forceinline__ u64 pack2f(float lo, float hi) {
    u64 r;
    asm("mov.b64 %0, {%1, %2};" : "=l"(r) : "r"(__float_as_uint(lo)), "r"(__float_as_uint(hi)));
    return r;
}
__device__ __forceinline__ u64 dup2f(float v) {
    u64 r;
    unsigned int u = __float_as_uint(v);
    asm("mov.b64 %0, {%1, %1};" : "=l"(r) : "r"(u));
    return r;
}
__device__ __forceinline__ void unpack2f(u64 p, float& lo, float& hi) {
    unsigned int a, b;
    asm("mov.b64 {%0, %1}, %2;" : "=r"(a), "=r"(b) : "l"(p));
    lo = __uint_as_float(a);
    hi = __uint_as_float(b);
}
__device__ __forceinline__ u64 fma2(u64 a, u64 b, u64 c) {
    u64 d;
    asm("fma.rn.f32x2 %0, %1, %2, %3;" : "=l"(d) : "l"(a), "l"(b), "l"(c));
    return d;
}

// ============================================================================
// Prep: block 0 -> AtA + step = 1/||AtA||_2 (power iteration) + mu table;
//       blocks 1..128 -> -A^T X with f32x2-packed row-pair accumulators
//       (FMA cost halved; chains remain per-row, same m-order -> bit-identical).
// ============================================================================
__global__ void __launch_bounds__(256) prep_kernel(const float* __restrict__ X,
                                                   const float* __restrict__ A) {
    const int tid = threadIdx.x;

    if (blockIdx.x == 0) {
        __shared__ float sAtA[KK][KK];
        const int j = tid & 31;
        const int i0 = (tid >> 5) * 4;       // 8 warps x 4 rows = 32 rows
        float a0 = 0.f, a1 = 0.f, a2 = 0.f, a3 = 0.f;
        for (int m = 0; m < MM; m++) {
            float aj = A[m * KK + j];
            a0 = fmaf(A[m * KK + i0 + 0], aj, a0);
            a1 = fmaf(A[m * KK + i0 + 1], aj, a1);
            a2 = fmaf(A[m * KK + i0 + 2], aj, a2);
            a3 = fmaf(A[m * KK + i0 + 3], aj, a3);
        }
        sAtA[i0 + 0][j] = a0;  g_AtA[i0 + 0][j] = a0;
        sAtA[i0 + 1][j] = a1;  g_AtA[i0 + 1][j] = a1;
        sAtA[i0 + 2][j] = a2;  g_AtA[i0 + 2][j] = a2;
        sAtA[i0 + 3][j] = a3;  g_AtA[i0 + 3][j] = a3;
        __syncthreads();

        if (tid < 32) {                       // power iteration, lane l holds v[l]
            const int l = tid;
            float v = 1.0f, lam = 1.0f;
            for (int it = 0; it < POWER_ITERS; it++) {
                float w = 0.0f;
                #pragma unroll
                for (int jj = 0; jj < 32; jj++) {
                    float vj = __shfl_sync(0xffffffffu, v, jj);
                    w = fmaf(sAtA[l][jj], vj, w);
                }
                float n2 = w * w;
                #pragma unroll
                for (int o = 16; o; o >>= 1)
                    n2 += __shfl_xor_sync(0xffffffffu, n2, o);
                lam = sqrtf(n2);
                v = w / lam;
            }
            if (l == 0) g_step = 1.0f / lam;
        } else if (tid == 32) {               // momentum table (serial, tiny)
            float t = 1.0f;
            for (int it = 0; it < NITER; it++) {
                float tn = 0.5f * (1.0f + sqrtf(fmaf(4.0f * t, t, 1.0f)));
                g_mu[it] = (t - 1.0f) / tn;
                t = tn;
            }
        }
    } else {
        // -A^T X: one thread per column n; A staged in shared as packed row
        // pairs; accumulators are 16 f32x2 chains (rows 2i, 2i+1 per chain).
        __shared__ __align__(16) u64 sAp[64][16];  // [m][i2] = (A[m][2i2], A[m][2i2+1])
        const int n = (blockIdx.x - 1) * 256 + tid;
        const u64* A2 = (const u64*)A;             // float pairs, 8B aligned

        u64 acc[16];
        #pragma unroll
        for (int i2 = 0; i2 < 16; i2++) acc[i2] = 0ull;

        for (int m0 = 0; m0 < MM; m0 += 64) {
            __syncthreads();
            #pragma unroll
            for (int k = 0; k < 4; k++) {
                int idx = tid + k * 256;      // 1024 u64 entries
                int m = idx >> 4, i2 = idx & 15;
                sAp[m][i2] = A2[(m0 + m) * 16 + i2];
            }
            __syncthreads();
            #pragma unroll 8
            for (int m = 0; m < 64; m++) {
                float x = X[(m0 + m) * NN + n];
                u64 xx = dup2f(x);
                #pragma unroll
                for (int i2 = 0; i2 < 16; i2++)
                    acc[i2] = fma2(sAp[m][i2], xx, acc[i2]);
            }
        }
        #pragma unroll
        for (int i2 = 0; i2 < 16; i2++) {
            float lo, hi;
            unpack2f(acc[i2], lo, hi);
            g_nAtX[2 * i2 + 0][n] = -lo;
            g_nAtX[2 * i2 + 1][n] = -hi;
        }
    }
}

// ============================================================================
// FISTA (R7 structure, measured best): warp owns a 16-column stripe and all
// 32 rows; thread = 4 rows x 4 cols; its 4 AtA rows in 128 registers; per j
// ONE LDS.128 of y feeds 16 FMAs (8 FFMA2, col-pairs packed in f32x2).
// Single-buffered y tile, two __syncwarp per iteration.
// ============================================================================
__global__ void __launch_bounds__(128) fista_kernel(float* __restrict__ out) {
    __shared__ float sY[4][KK][YS];           // per-warp y tile (single buffer)
    __shared__ float smu[NITER];

    const int tid = threadIdx.x;
    const int w = tid >> 5;                   // warp id 0..3
    const int lane = tid & 31;
    const int rg = lane >> 2;                 // rowgroup 0..7 -> rows 4rg..4rg+3
    const int hg = lane & 3;                  // colgroup 0..3 -> cols 4hg..4hg+3
    const int r0 = 4 * rg;
    const int c0 = 4 * hg;
    const int n0 = blockIdx.x * 64 + w * 16 + c0;

    // this thread's 4 AtA rows in registers (128 regs)
    float a[4][32];
    #pragma unroll
    for (int r = 0; r < 4; r++) {
        #pragma unroll
        for (int q = 0; q < 8; q++) {
            float4 v = ((const float4*)g_AtA[r0 + r])[q];
            a[r][4 * q + 0] = v.x; a[r][4 * q + 1] = v.y;
            a[r][4 * q + 2] = v.z; a[r][4 * q + 3] = v.w;
        }
    }

    // -AtX for this thread's 4x4 patch, packed as col-pairs
    u64 nx[4][2];
    #pragma unroll
    for (int r = 0; r < 4; r++) {
        float4 v = *(const float4*)&g_nAtX[r0 + r][n0];
        nx[r][0] = pack2f(v.x, v.y);
        nx[r][1] = pack2f(v.z, v.w);
    }

    #pragma unroll
    for (int i = tid; i < NITER; i += 128) smu[i] = g_mu[i];

    // zero this thread's y entries
    const float4 zero4 = make_float4(0.f, 0.f, 0.f, 0.f);
    #pragma unroll
    for (int r = 0; r < 4; r++)
        *(float4*)&sY[w][r0 + r][c0] = zero4;

    const float nstep = -g_step;
    __syncthreads();                          // smu + initial y visible

    float s[4][4], yo[4][4];
    #pragma unroll
    for (int r = 0; r < 4; r++)
        #pragma unroll
        for (int k = 0; k < 4; k++) { s[r][k] = 0.0f; yo[r][k] = 0.0f; }

    #pragma unroll 1
    for (int it = 0; it < NITER; it++) {
        u64 z[4][2];
        #pragma unroll
        for (int r = 0; r < 4; r++) { z[r][0] = nx[r][0]; z[r][1] = nx[r][1]; }

        #pragma unroll
        for (int j = 0; j < 32; j++) {
            // one LDS.128: y[j] for this thread's 4 cols
            ulonglong2 yy = *(const ulonglong2*)&sY[w][j][c0];
            u64 d0 = dup2f(a[0][j]);
            u64 d1 = dup2f(a[1][j]);
            u64 d2 = dup2f(a[2][j]);
            u64 d3 = dup2f(a[3][j]);
            z[0][0] = fma2(d0, yy.x, z[0][0]);  z[0][1] = fma2(d0, yy.y, z[0][1]);
            z[1][0] = fma2(d1, yy.x, z[1][0]);  z[1][1] = fma2(d1, yy.y, z[1][1]);
            z[2][0] = fma2(d2, yy.x, z[2][0]);  z[2][1] = fma2(d2, yy.y, z[2][1]);
            z[3][0] = fma2(d3, yy.x, z[3][0]);  z[3][1] = fma2(d3, yy.y, z[3][1]);
        }

        const float mu = smu[it];

        __syncwarp();                         // all lanes done reading old y
        #pragma unroll
        for (int r = 0; r < 4; r++) {
            float zv[4];
            unpack2f(z[r][0], zv[0], zv[1]);
            unpack2f(z[r][1], zv[2], zv[3]);
            float4 yn;
            float sn;
            sn = fmaxf(fmaf(nstep, zv[0], yo[r][0]), 0.f); yn.x = fmaf(mu, sn - s[r][0], sn); s[r][0] = sn; yo[r][0] = yn.x;
            sn = fmaxf(fmaf(nstep, zv[1], yo[r][1]), 0.f); yn.y = fmaf(mu, sn - s[r][1], sn); s[r][1] = sn; yo[r][1] = yn.y;
            sn = fmaxf(fmaf(nstep, zv[2], yo[r][2]), 0.f); yn.z = fmaf(mu, sn - s[r][2], sn); s[r][2] = sn; yo[r][2] = yn.z;
            sn = fmaxf(fmaf(nstep, zv[3], yo[r][3]), 0.f); yn.w = fmaf(mu, sn - s[r][3], sn); s[r][3] = sn; yo[r][3] = yn.w;
            *(float4*)&sY[w][r0 + r][c0] = yn;
        }
        __syncwarp();                         // new y visible before next matvec
    }

    // S is [32, 32768] row-major
    #pragma unroll
    for (int r = 0; r < 4; r++) {
        float4 v = make_float4(s[r][0], s[r][1], s[r][2], s[r][3]);
        *(float4*)&out[(r0 + r) * NN + n0] = v;
    }
}

// ============================================================================
extern "C" void kernel_launch(void* const* d_in, const int* in_sizes, int n_in,
                              void* d_out, int out_size) {
    const float* X = (const float*)d_in[0];
    const float* A = (const float*)d_in[1];
    // defensive: identify A by its element count (512*32 = 16384)
    if (n_in >= 2 && in_sizes[0] == MM * KK && in_sizes[1] != MM * KK) {
        A = (const float*)d_in[0];
        X = (const float*)d_in[1];
    }

    prep_kernel<<<1 + NN / 256, 256>>>(X, A);
    fista_kernel<<<NN / 64, 128>>>((float*)d_out);
}

// round 14
// speedup vs baseline: 1.0162x; 1.0162x over previous
#include <cuda_runtime.h>

#define NN 32768   // columns
#define MM 512     // rows of A / X
#define KK 32      // inner dim / output rows
#define NITER 200  // must match reference trajectory exactly
#define POWER_ITERS 40
#define YS 36      // sY row stride in floats

typedef unsigned long long u64;

// ---- device-global scratch (no allocations allowed) ----
__device__ float g_step;
__device__ float g_mu[NITER];                   // precomputed Nesterov momentum factors
__device__ __align__(16) float g_AtA[KK][KK];   // symmetric Gram matrix
__device__ float g_nAtX[KK][NN];                // negated A^T X, row-major

// ---- packed f32x2 helpers (sm_100a) ----
__device__ __forceinline__ u64 pack2f(float lo, float hi) {
    u64 r;
    asm("mov.b64 %0, {%1, %2};" : "=l"(r) : "r"(__float_as_uint(lo)), "r"(__float_as_uint(hi)));
    return r;
}
__device__ __forceinline__ u64 dup2f(float v) {
    u64 r;
    unsigned int u = __float_as_uint(v);
    asm("mov.b64 %0, {%1, %1};" : "=l"(r) : "r"(u));
    return r;
}
__device__ __forceinline__ void unpack2f(u64 p, float& lo, float& hi) {
    unsigned int a, b;
    asm("mov.b64 {%0, %1}, %2;" : "=r"(a), "=r"(b) : "l"(p));
    lo = __uint_as_float(a);
    hi = __uint_as_float(b);
}
__device__ __forceinline__ u64 fma2(u64 a, u64 b, u64 c) {
    u64 d;
    asm("fma.rn.f32x2 %0, %1, %2, %3;" : "=l"(d) : "l"(a), "l"(b), "l"(c));
    return d;
}
__device__ __forceinline__ u64 add2(u64 a, u64 b) {
    u64 d;
    asm("add.rn.f32x2 %0, %1, %2;" : "=l"(d) : "l"(a), "l"(b));
    return d;
}
// relu on both packed halves (register-pair aliasing; FMNMX on alu pipe)
__device__ __forceinline__ u64 relu2(u64 p) {
    float lo, hi;
    unpack2f(p, lo, hi);
    return pack2f(fmaxf(lo, 0.0f), fmaxf(hi, 0.0f));
}

// ============================================================================
// Prep: block 0 -> AtA + step = 1/||AtA||_2 (power iteration) + mu table;
//       blocks 1..128 -> -A^T X, LDS.128 A-tile reads + f32x2 accumulators.
// ============================================================================
__global__ void __launch_bounds__(256) prep_kernel(const float* __restrict__ X,
                                                   const float* __restrict__ A) {
    const int tid = threadIdx.x;

    if (blockIdx.x == 0) {
        __shared__ float sAtA[KK][KK];
        const int j = tid & 31;
        const int i0 = (tid >> 5) * 4;       // 8 warps x 4 rows = 32 rows
        float a0 = 0.f, a1 = 0.f, a2 = 0.f, a3 = 0.f;
        for (int m = 0; m < MM; m++) {
            float aj = A[m * KK + j];
            a0 = fmaf(A[m * KK + i0 + 0], aj, a0);
            a1 = fmaf(A[m * KK + i0 + 1], aj, a1);
            a2 = fmaf(A[m * KK + i0 + 2], aj, a2);
            a3 = fmaf(A[m * KK + i0 + 3], aj, a3);
        }
        sAtA[i0 + 0][j] = a0;  g_AtA[i0 + 0][j] = a0;
        sAtA[i0 + 1][j] = a1;  g_AtA[i0 + 1][j] = a1;
        sAtA[i0 + 2][j] = a2;  g_AtA[i0 + 2][j] = a2;
        sAtA[i0 + 3][j] = a3;  g_AtA[i0 + 3][j] = a3;
        __syncthreads();

        if (tid < 32) {                       // power iteration, lane l holds v[l]
            const int l = tid;
            float v = 1.0f, lam = 1.0f;
            for (int it = 0; it < POWER_ITERS; it++) {
                float w = 0.0f;
                #pragma unroll
                for (int jj = 0; jj < 32; jj++) {
                    float vj = __shfl_sync(0xffffffffu, v, jj);
                    w = fmaf(sAtA[l][jj], vj, w);
                }
                float n2 = w * w;
                #pragma unroll
                for (int o = 16; o; o >>= 1)
                    n2 += __shfl_xor_sync(0xffffffffu, n2, o);
                lam = sqrtf(n2);
                v = w / lam;
            }
            if (l == 0) g_step = 1.0f / lam;
        } else if (tid == 32) {               // momentum table (serial, tiny)
            float t = 1.0f;
            for (int it = 0; it < NITER; it++) {
                float tn = 0.5f * (1.0f + sqrtf(fmaf(4.0f * t, t, 1.0f)));
                g_mu[it] = (t - 1.0f) / tn;
                t = tn;
            }
        }
    } else {
        // -A^T X: one thread per column n; A staged in shared as packed row
        // pairs, READ AS LDS.128 (8 per m, not 16 LDS.64 -> LSU halved).
        __shared__ __align__(16) u64 sAp[64][16];  // [m][i2] = (A[m][2i2], A[m][2i2+1])
        const int n = (blockIdx.x - 1) * 256 + tid;
        const u64* A2 = (const u64*)A;             // float pairs, 8B aligned

        u64 acc[16];
        #pragma unroll
        for (int i2 = 0; i2 < 16; i2++) acc[i2] = 0ull;

        for (int m0 = 0; m0 < MM; m0 += 64) {
            __syncthreads();
            #pragma unroll
            for (int k = 0; k < 4; k++) {
                int idx = tid + k * 256;      // 1024 u64 entries
                int m = idx >> 4, i2 = idx & 15;
                sAp[m][i2] = A2[(m0 + m) * 16 + i2];
            }
            __syncthreads();
            #pragma unroll 8
            for (int m = 0; m < 64; m++) {
                float x = X[(m0 + m) * NN + n];
                u64 xx = dup2f(x);
                const ulonglong2* row = (const ulonglong2*)sAp[m];  // 8 x LDS.128
                #pragma unroll
                for (int q = 0; q < 8; q++) {
                    ulonglong2 ap = row[q];
                    acc[2 * q + 0] = fma2(ap.x, xx, acc[2 * q + 0]);
                    acc[2 * q + 1] = fma2(ap.y, xx, acc[2 * q + 1]);
                }
            }
        }
        #pragma unroll
        for (int i2 = 0; i2 < 16; i2++) {
            float lo, hi;
            unpack2f(acc[i2], lo, hi);
            g_nAtX[2 * i2 + 0][n] = -lo;
            g_nAtX[2 * i2 + 1][n] = -hi;
        }
    }
}

// ============================================================================
// FISTA (R7 matvec, packed f32x2 epilogue): warp owns 16 cols x 32 rows;
// thread = 4 rows x 4 cols; 4 AtA rows in 128 regs; per j ONE LDS.128 of y
// feeds 8 FFMA2. Epilogue fully packed: state yo2 (=y) and ns (=-s, exact
// sign-flip) as u64 col-pairs; sub becomes add2(sn, ns) -> bit-identical.
// ============================================================================
__global__ void __launch_bounds__(128) fista_kernel(float* __restrict__ out) {
    __shared__ __align__(16) float sY[4][KK][YS]; // per-warp y tile
    __shared__ float smu[NITER];

    const int tid = threadIdx.x;
    const int w = tid >> 5;                   // warp id 0..3
    const int lane = tid & 31;
    const int rg = lane >> 2;                 // rowgroup 0..7 -> rows 4rg..4rg+3
    const int hg = lane & 3;                  // colgroup 0..3 -> cols 4hg..4hg+3
    const int r0 = 4 * rg;
    const int c0 = 4 * hg;
    const int n0 = blockIdx.x * 64 + w * 16 + c0;

    // this thread's 4 AtA rows in registers (128 regs)
    float a[4][32];
    #pragma unroll
    for (int r = 0; r < 4; r++) {
        #pragma unroll
        for (int q = 0; q < 8; q++) {
            float4 v = ((const float4*)g_AtA[r0 + r])[q];
            a[r][4 * q + 0] = v.x; a[r][4 * q + 1] = v.y;
            a[r][4 * q + 2] = v.z; a[r][4 * q + 3] = v.w;
        }
    }

    // -AtX for this thread's 4x4 patch, packed as col-pairs
    u64 nx[4][2];
    #pragma unroll
    for (int r = 0; r < 4; r++) {
        float4 v = *(const float4*)&g_nAtX[r0 + r][n0];
        nx[r][0] = pack2f(v.x, v.y);
        nx[r][1] = pack2f(v.z, v.w);
    }

    #pragma unroll
    for (int i = tid; i < NITER; i += 128) smu[i] = g_mu[i];

    // zero this thread's y entries
    const float4 zero4 = make_float4(0.f, 0.f, 0.f, 0.f);
    #pragma unroll
    for (int r = 0; r < 4; r++)
        *(float4*)&sY[w][r0 + r][c0] = zero4;

    const u64 nstep2 = dup2f(-g_step);        // dup'd once
    __syncthreads();                          // smu + initial y visible

    // packed state: yo2 = y (col-pairs), ns = -s (exact negation)
    u64 yo2[4][2], ns[4][2];
    #pragma unroll
    for (int r = 0; r < 4; r++) {
        yo2[r][0] = 0ull; yo2[r][1] = 0ull;
        ns[r][0] = 0ull;  ns[r][1] = 0ull;    // -0 == +0 additively
    }

    #pragma unroll 1
    for (int it = 0; it < NITER; it++) {
        u64 z[4][2];
        #pragma unroll
        for (int r = 0; r < 4; r++) { z[r][0] = nx[r][0]; z[r][1] = nx[r][1]; }

        #pragma unroll
        for (int j = 0; j < 32; j++) {
            // one LDS.128: y[j] for this thread's 4 cols
            ulonglong2 yy = *(const ulonglong2*)&sY[w][j][c0];
            u64 d0 = dup2f(a[0][j]);
            u64 d1 = dup2f(a[1][j]);
            u64 d2 = dup2f(a[2][j]);
            u64 d3 = dup2f(a[3][j]);
            z[0][0] = fma2(d0, yy.x, z[0][0]);  z[0][1] = fma2(d0, yy.y, z[0][1]);
            z[1][0] = fma2(d1, yy.x, z[1][0]);  z[1][1] = fma2(d1, yy.y, z[1][1]);
            z[2][0] = fma2(d2, yy.x, z[2][0]);  z[2][1] = fma2(d2, yy.y, z[2][1]);
            z[3][0] = fma2(d3, yy.x, z[3][0]);  z[3][1] = fma2(d3, yy.y, z[3][1]);
        }

        const u64 mu2 = dup2f(smu[it]);

        __syncwarp();                         // all lanes done reading old y
        #pragma unroll
        for (int r = 0; r < 4; r++) {
            #pragma unroll
            for (int h = 0; h < 2; h++) {
                u64 sn = relu2(fma2(nstep2, z[r][h], yo2[r][h]));  // max(y - step*z, 0)
                u64 diff = add2(sn, ns[r][h]);                     // sn - s (exact)
                yo2[r][h] = fma2(mu2, diff, sn);                   // y = sn + mu*diff
                ns[r][h] = sn ^ 0x8000000080000000ull;             // -sn (sign flip)
            }
            ulonglong2 yw;
            yw.x = yo2[r][0]; yw.y = yo2[r][1];
            *(ulonglong2*)&sY[w][r0 + r][c0] = yw;                 // STS.128
        }
        __syncwarp();                         // new y visible before next matvec
    }

    // S = -ns, [32, 32768] row-major
    #pragma unroll
    for (int r = 0; r < 4; r++) {
        ulonglong2 sw;
        sw.x = ns[r][0] ^ 0x8000000080000000ull;
        sw.y = ns[r][1] ^ 0x8000000080000000ull;
        *(ulonglong2*)&out[(r0 + r) * NN + n0] = sw;
    }
}

// ============================================================================
extern "C" void kernel_launch(void* const* d_in, const int* in_sizes, int n_in,
                              void* d_out, int out_size) {
    const float* X = (const float*)d_in[0];
    const float* A = (const float*)d_in[1];
    // defensive: identify A by its element count (512*32 = 16384)
    if (n_in >= 2 && in_sizes[0] == MM * KK && in_sizes[1] != MM * KK) {
        A = (const float*)d_in[0];
        X = (const float*)d_in[1];
    }

    prep_kernel<<<1 + NN / 256, 256>>>(X, A);
    fista_kernel<<<NN / 64, 128>>>((float*)d_out);
}